// round 13
// baseline (speedup 1.0000x reference)
#include <cuda_runtime.h>
#include <cuda_fp16.h>
#include <math.h>
#include <stdint.h>

// ---------------- problem constants ----------------
#define NB   2
#define DD   192
#define NHH  8
#define HDD  24
#define H0c  96
#define W0c  96
#define H1c  48
#define W1c  48
#define N0c  (H0c*W0c)      // 9216
#define N1c  (H1c*W1c)      // 2304
#define LTc  (N0c+N1c)      // 11520
#define MT   (NB*LTc)       // 23040
#define FFc  256
#define NLAY 6

#define LN_SMEM (15360 + 38400)   // dynamic smem for k_gemm_ln (3-stage)

// ---------------- device scratch ----------------
__device__ float  g_src  [MT*DD];      // running activation (fp32 exact trunk)
__device__ float  g_srnd [MT*DD];      // rna(src)  — GEMM A input
__device__ float  g_qrnd [MT*DD];      // rna(src+pos) — GEMM A input
__device__ float  g_pos  [LTc*DD];
__device__ float  g_ref  [LTc*2];
__device__ float  g_offaw[MT*DD];      // offsets(128) + aw logits(64)
__device__ __half g_vh   [MT*DD];      // value projection, fp16 (halves gather traffic)
__device__ float  g_attn [MT*DD];      // rna-rounded
__device__ float  g_ffn  [MT*FFc];     // rna-rounded
__device__ float  g_wcomb[NLAY*DD*DD]; // rna(so_W || aw_W)
__device__ float  g_bcomb[NLAY*DD];
__device__ float  g_wv   [NLAY*DD*DD];
__device__ float  g_wo   [NLAY*DD*DD];
__device__ float  g_w1   [NLAY*DD*FFc];
__device__ float  g_w2   [NLAY*FFc*DD];
__device__ float  g_ps   [512];        // GN partial sums
__device__ float  g_ps2  [512];        // GN partial sumsq

// ---------------- helpers ----------------
__device__ __forceinline__ uint32_t f2tf32(float x) {
    uint32_t r;
    asm("cvt.rna.tf32.f32 %0, %1;" : "=r"(r) : "f"(x));
    return r;
}
__device__ __forceinline__ float rnd(float x) { return __uint_as_float(f2tf32(x)); }

__device__ __forceinline__ void mma_tf32(float* c, const uint32_t* a, const uint32_t* b) {
    asm volatile(
        "mma.sync.aligned.m16n8k8.row.col.f32.tf32.tf32.f32 "
        "{%0,%1,%2,%3}, {%4,%5,%6,%7}, {%8,%9}, {%0,%1,%2,%3};"
        : "+f"(c[0]), "+f"(c[1]), "+f"(c[2]), "+f"(c[3])
        : "r"(a[0]), "r"(a[1]), "r"(a[2]), "r"(a[3]), "r"(b[0]), "r"(b[1]));
}
__device__ __forceinline__ uint32_t s2u(const void* p) {
    return (uint32_t)__cvta_generic_to_shared(p);
}
__device__ __forceinline__ void cp16(uint32_t dst, const void* src) {
    asm volatile("cp.async.cg.shared.global [%0], [%1], 16;" :: "r"(dst), "l"(src));
}
__device__ __forceinline__ void cp_commit() { asm volatile("cp.async.commit_group;"); }
template<int W> __device__ __forceinline__ void cp_wait() {
    asm volatile("cp.async.wait_group %0;" :: "n"(W));
}

// ---------------- fused init: weight prep + pos embed + ref pts (ONE launch) -
__global__ void k_init(const float* __restrict__ soW, const float* __restrict__ sob,
                       const float* __restrict__ awW, const float* __restrict__ awb,
                       const float* __restrict__ vpW, const float* __restrict__ opW,
                       const float* __restrict__ l1W, const float* __restrict__ l2W,
                       const float* __restrict__ level_embed) {
    int idx = blockIdx.x * blockDim.x + threadIdx.x;
    const int SZ1 = NLAY * DD * DD;
    const int SZ2 = NLAY * DD * FFc;
    if (idx < SZ1) {
        int i = idx / (DD * DD);
        int rem = idx % (DD * DD);
        int k = rem / DD, n = rem % DD;
        float w = (n < 128) ? soW[(size_t)i * DD * 128 + k * 128 + n]
                            : awW[(size_t)i * DD * 64 + k * 64 + (n - 128)];
        g_wcomb[idx] = rnd(w);
        g_wv[idx] = rnd(vpW[idx]);
        g_wo[idx] = rnd(opW[idx]);
    }
    if (idx < SZ2) {
        g_w1[idx] = rnd(l1W[idx]);
        g_w2[idx] = rnd(l2W[idx]);
    }
    if (idx < NLAY * DD) {
        int i = idx / DD, n = idx % DD;
        g_bcomb[idx] = (n < 128) ? sob[i * 128 + n] : awb[i * 64 + (n - 128)];
    }
    if (idx < LTc * DD) {
        int l = idx / DD, d = idx % DD;
        int lev, i, j, Hc, Wc;
        if (l < N0c) { lev = 0; i = l / W0c; j = l % W0c; Hc = H0c; Wc = W0c; }
        else         { lev = 1; int ll = l - N0c; i = ll / W1c; j = ll % W1c; Hc = H1c; Wc = W1c; }
        const float TWO_PI = 6.283185307179586f;
        float v; int dd;
        if (d < 96) { v = ((float)i + 0.5f) / ((float)Hc + 1e-6f) * TWO_PI; dd = d; }
        else        { v = ((float)j + 0.5f) / ((float)Wc + 1e-6f) * TWO_PI; dd = d - 96; }
        float e = (float)(2 * (dd >> 1)) / 96.0f;
        float t = v / powf(10000.0f, e);
        float val = (dd & 1) ? cosf(t) : sinf(t);
        g_pos[idx] = val + level_embed[lev * DD + d];
        if (d == 0) {
            g_ref[l * 2 + 0] = ((float)j + 0.5f) / (float)Wc;
            g_ref[l * 2 + 1] = ((float)i + 0.5f) / (float)Hc;
        }
    }
}

// ---------------- main TF32 GEMM: BM=64, BN=64, 128 thr, 3-stage cp.async ----
template <bool RELU, bool ROUND>
__global__ __launch_bounds__(128) void k_gemm_main(
    const float* __restrict__ A, const float* __restrict__ Bm,
    const float* __restrict__ bias, float* __restrict__ C,
    int N, int K)
{
    __shared__ float As[3][64][20];
    __shared__ float Bs[3][16][72];
    const int bm = blockIdx.y * 64, bn = blockIdx.x * 64;
    const int tid = threadIdx.x;
    const int warp = tid >> 5, lane = tid & 31;
    const int wm = (warp >> 1) * 32, wn = (warp & 1) * 32;
    const int g = lane >> 2, tig = lane & 3;
    const float* Ag = A + (size_t)bm * K;

    float acc[2][4][4];
    #pragma unroll
    for (int t = 0; t < 2; t++)
        #pragma unroll
        for (int u = 0; u < 4; u++)
            #pragma unroll
            for (int r = 0; r < 4; r++) acc[t][u][r] = 0.f;

    const int mA = tid >> 2, cA = (tid & 3) * 4;
    const int kB = tid >> 4, cB = (tid & 15) * 4;

    auto load_stage = [&](int st, int kk) {
        cp16(s2u(&As[st][mA][cA]),      Ag + (size_t)mA * K + kk + cA);
        cp16(s2u(&As[st][mA + 32][cA]), Ag + (size_t)(mA + 32) * K + kk + cA);
        cp16(s2u(&Bs[st][kB][cB]),      Bm + (size_t)(kk + kB) * N + bn + cB);
        cp16(s2u(&Bs[st][kB + 8][cB]),  Bm + (size_t)(kk + kB + 8) * N + bn + cB);
    };

    const int niter = K / 16;
    load_stage(0, 0);  cp_commit();
    load_stage(1, 16); cp_commit();
    cp_wait<1>();
    __syncthreads();

    for (int it = 0; it < niter; it++) {
        if (it + 2 < niter) load_stage((it + 2) % 3, (it + 2) * 16);
        cp_commit();
        const int buf = it % 3;
        #pragma unroll
        for (int s = 0; s < 16; s += 8) {
            uint32_t af[2][4], bf[4][2];
            #pragma unroll
            for (int t = 0; t < 2; t++) {
                af[t][0] = __float_as_uint(As[buf][wm + t * 16 + g    ][s + tig]);
                af[t][1] = __float_as_uint(As[buf][wm + t * 16 + g + 8][s + tig]);
                af[t][2] = __float_as_uint(As[buf][wm + t * 16 + g    ][s + tig + 4]);
                af[t][3] = __float_as_uint(As[buf][wm + t * 16 + g + 8][s + tig + 4]);
            }
            #pragma unroll
            for (int u = 0; u < 4; u++) {
                bf[u][0] = __float_as_uint(Bs[buf][s + tig    ][wn + u * 8 + g]);
                bf[u][1] = __float_as_uint(Bs[buf][s + tig + 4][wn + u * 8 + g]);
            }
            #pragma unroll
            for (int t = 0; t < 2; t++)
                #pragma unroll
                for (int u = 0; u < 4; u++)
                    mma_tf32(acc[t][u], af[t], bf[u]);
        }
        cp_wait<1>();
        __syncthreads();
    }

    #pragma unroll
    for (int t = 0; t < 2; t++) {
        int row0 = bm + wm + t * 16 + g;
        int row1 = row0 + 8;
        #pragma unroll
        for (int u = 0; u < 4; u++) {
            int col = bn + wn + u * 8 + tig * 2;
            float b0 = bias[col], b1 = bias[col + 1];
            float2 v0 = make_float2(acc[t][u][0] + b0, acc[t][u][1] + b1);
            float2 v1 = make_float2(acc[t][u][2] + b0, acc[t][u][3] + b1);
            if (RELU) {
                v0.x = fmaxf(v0.x, 0.f); v0.y = fmaxf(v0.y, 0.f);
                v1.x = fmaxf(v1.x, 0.f); v1.y = fmaxf(v1.y, 0.f);
            }
            if (ROUND) {
                v0.x = rnd(v0.x); v0.y = rnd(v0.y);
                v1.x = rnd(v1.x); v1.y = rnd(v1.y);
            }
            *reinterpret_cast<float2*>(&C[(size_t)row0 * N + col]) = v0;
            *reinterpret_cast<float2*>(&C[(size_t)row1 * N + col]) = v1;
        }
    }
}

// ---------------- dual GEMM: offaw (z=0, fp32 out) and v (z=1, fp16 out) -----
__global__ __launch_bounds__(128) void k_gemm_dual(
    const float* __restrict__ A0, const float* __restrict__ B0,
    const float* __restrict__ b0p, float* __restrict__ C0,
    const float* __restrict__ A1, const float* __restrict__ B1,
    const float* __restrict__ b1p)
{
    const float* A  = blockIdx.z ? A1 : A0;
    const float* Bm = blockIdx.z ? B1 : B0;
    const float* bias = blockIdx.z ? b1p : b0p;
    const int N = DD, K = DD;

    __shared__ float As[3][64][20];
    __shared__ float Bs[3][16][72];
    const int bm = blockIdx.y * 64, bn = blockIdx.x * 64;
    const int tid = threadIdx.x;
    const int warp = tid >> 5, lane = tid & 31;
    const int wm = (warp >> 1) * 32, wn = (warp & 1) * 32;
    const int g = lane >> 2, tig = lane & 3;
    const float* Ag = A + (size_t)bm * K;

    float acc[2][4][4];
    #pragma unroll
    for (int t = 0; t < 2; t++)
        #pragma unroll
        for (int u = 0; u < 4; u++)
            #pragma unroll
            for (int r = 0; r < 4; r++) acc[t][u][r] = 0.f;

    const int mA = tid >> 2, cA = (tid & 3) * 4;
    const int kB = tid >> 4, cB = (tid & 15) * 4;

    auto load_stage = [&](int st, int kk) {
        cp16(s2u(&As[st][mA][cA]),      Ag + (size_t)mA * K + kk + cA);
        cp16(s2u(&As[st][mA + 32][cA]), Ag + (size_t)(mA + 32) * K + kk + cA);
        cp16(s2u(&Bs[st][kB][cB]),      Bm + (size_t)(kk + kB) * N + bn + cB);
        cp16(s2u(&Bs[st][kB + 8][cB]),  Bm + (size_t)(kk + kB + 8) * N + bn + cB);
    };

    const int niter = K / 16;
    load_stage(0, 0);  cp_commit();
    load_stage(1, 16); cp_commit();
    cp_wait<1>();
    __syncthreads();

    for (int it = 0; it < niter; it++) {
        if (it + 2 < niter) load_stage((it + 2) % 3, (it + 2) * 16);
        cp_commit();
        const int buf = it % 3;
        #pragma unroll
        for (int s = 0; s < 16; s += 8) {
            uint32_t af[2][4], bf[4][2];
            #pragma unroll
            for (int t = 0; t < 2; t++) {
                af[t][0] = __float_as_uint(As[buf][wm + t * 16 + g    ][s + tig]);
                af[t][1] = __float_as_uint(As[buf][wm + t * 16 + g + 8][s + tig]);
                af[t][2] = __float_as_uint(As[buf][wm + t * 16 + g    ][s + tig + 4]);
                af[t][3] = __float_as_uint(As[buf][wm + t * 16 + g + 8][s + tig + 4]);
            }
            #pragma unroll
            for (int u = 0; u < 4; u++) {
                bf[u][0] = __float_as_uint(Bs[buf][s + tig    ][wn + u * 8 + g]);
                bf[u][1] = __float_as_uint(Bs[buf][s + tig + 4][wn + u * 8 + g]);
            }
            #pragma unroll
            for (int t = 0; t < 2; t++)
                #pragma unroll
                for (int u = 0; u < 4; u++)
                    mma_tf32(acc[t][u], af[t], bf[u]);
        }
        cp_wait<1>();
        __syncthreads();
    }

    if (blockIdx.z == 0) {
        // offsets + aw logits: fp32 output
        #pragma unroll
        for (int t = 0; t < 2; t++) {
            int row0 = bm + wm + t * 16 + g;
            int row1 = row0 + 8;
            #pragma unroll
            for (int u = 0; u < 4; u++) {
                int col = bn + wn + u * 8 + tig * 2;
                float b0 = bias[col], b1 = bias[col + 1];
                *reinterpret_cast<float2*>(&C0[(size_t)row0 * N + col]) =
                    make_float2(acc[t][u][0] + b0, acc[t][u][1] + b1);
                *reinterpret_cast<float2*>(&C0[(size_t)row1 * N + col]) =
                    make_float2(acc[t][u][2] + b0, acc[t][u][3] + b1);
            }
        }
    } else {
        // value projection: fp16 output (halves deform gather traffic)
        #pragma unroll
        for (int t = 0; t < 2; t++) {
            int row0 = bm + wm + t * 16 + g;
            int row1 = row0 + 8;
            #pragma unroll
            for (int u = 0; u < 4; u++) {
                int col = bn + wn + u * 8 + tig * 2;
                float b0 = bias[col], b1 = bias[col + 1];
                __half2 h0 = __floats2half2_rn(acc[t][u][0] + b0, acc[t][u][1] + b1);
                __half2 h1 = __floats2half2_rn(acc[t][u][2] + b0, acc[t][u][3] + b1);
                *reinterpret_cast<__half2*>(&g_vh[(size_t)row0 * N + col]) = h0;
                *reinterpret_cast<__half2*>(&g_vh[(size_t)row1 * N + col]) = h1;
            }
        }
    }
}

// ---------------- TF32 GEMM + residual + LayerNorm, 3-stage cp.async --------
template <bool WRITEQ>
__global__ __launch_bounds__(256) void k_gemm_ln(
    const float* __restrict__ A, const float* __restrict__ Bm,
    const float* __restrict__ bias,
    const float* __restrict__ gamma, const float* __restrict__ beta,
    int K)
{
    extern __shared__ __align__(16) char sbuf[];
    float (*As)[64][20]  = reinterpret_cast<float(*)[64][20]>(sbuf);
    float (*Bs)[16][200] = reinterpret_cast<float(*)[16][200]>(sbuf + 15360);

    const int bm = blockIdx.x * 64;
    const int tid = threadIdx.x;
    const int warp = tid >> 5, lane = tid & 31;
    const int wm = (warp >> 2) * 32, wn = (warp & 3) * 48;
    const int g = lane >> 2, tig = lane & 3;
    const float* Ag = A + (size_t)bm * K;

    float acc[2][6][4];
    #pragma unroll
    for (int t = 0; t < 2; t++)
        #pragma unroll
        for (int u = 0; u < 6; u++)
            #pragma unroll
            for (int r = 0; r < 4; r++) acc[t][u][r] = 0.f;

    const int mA = tid >> 2, cA = (tid & 3) * 4;

    auto load_stage = [&](int st, int kk) {
        cp16(s2u(&As[st][mA][cA]), Ag + (size_t)mA * K + kk + cA);
        #pragma unroll
        for (int j = 0; j < 3; j++) {
            int idx = tid + j * 256;
            int k = idx / 48, n4 = (idx % 48) * 4;
            cp16(s2u(&Bs[st][k][n4]), Bm + (size_t)(kk + k) * DD + n4);
        }
    };

    const int niter = K / 16;
    load_stage(0, 0);  cp_commit();
    load_stage(1, 16); cp_commit();
    cp_wait<1>();
    __syncthreads();

    for (int it = 0; it < niter; it++) {
        if (it + 2 < niter) load_stage((it + 2) % 3, (it + 2) * 16);
        cp_commit();
        const int buf = it % 3;
        #pragma unroll
        for (int s = 0; s < 16; s += 8) {
            uint32_t af[2][4], bf[6][2];
            #pragma unroll
            for (int t = 0; t < 2; t++) {
                af[t][0] = __float_as_uint(As[buf][wm + t * 16 + g    ][s + tig]);
                af[t][1] = __float_as_uint(As[buf][wm + t * 16 + g + 8][s + tig]);
                af[t][2] = __float_as_uint(As[buf][wm + t * 16 + g    ][s + tig + 4]);
                af[t][3] = __float_as_uint(As[buf][wm + t * 16 + g + 8][s + tig + 4]);
            }
            #pragma unroll
            for (int u = 0; u < 6; u++) {
                bf[u][0] = __float_as_uint(Bs[buf][s + tig    ][wn + u * 8 + g]);
                bf[u][1] = __float_as_uint(Bs[buf][s + tig + 4][wn + u * 8 + g]);
            }
            #pragma unroll
            for (int t = 0; t < 2; t++)
                #pragma unroll
                for (int u = 0; u < 6; u++)
                    mma_tf32(acc[t][u], af[t], bf[u]);
        }
        cp_wait<1>();
        __syncthreads();
    }

    // ---- fused epilogue: x = acc + bias + res; LayerNorm per row ----
    float* psum  = reinterpret_cast<float*>(sbuf);   // [64][18]
    float* psum2 = psum + 64 * 18;                   // [64][18]
    float* smu   = psum2 + 64 * 18;                  // [64]
    float* srstd = smu + 64;                         // [64]
    const int widx = (warp & 3) * 4 + tig;

    #pragma unroll
    for (int t = 0; t < 2; t++) {
        #pragma unroll
        for (int half = 0; half < 2; half++) {
            int row = wm + t * 16 + g + half * 8;
            const float* rr = g_src + (size_t)(bm + row) * DD;
            float s = 0.f, s2 = 0.f;
            #pragma unroll
            for (int u = 0; u < 6; u++) {
                int col = wn + u * 8 + tig * 2;
                float2 rv = *reinterpret_cast<const float2*>(&rr[col]);
                float x0 = acc[t][u][half * 2 + 0] + bias[col]     + rv.x;
                float x1 = acc[t][u][half * 2 + 1] + bias[col + 1] + rv.y;
                acc[t][u][half * 2 + 0] = x0;
                acc[t][u][half * 2 + 1] = x1;
                s += x0 + x1;
                s2 += x0 * x0 + x1 * x1;
            }
            psum [row * 18 + widx] = s;
            psum2[row * 18 + widx] = s2;
        }
    }
    __syncthreads();
    if (tid < 64) {
        float s = 0.f, s2 = 0.f;
        #pragma unroll
        for (int j = 0; j < 16; j++) { s += psum[tid * 18 + j]; s2 += psum2[tid * 18 + j]; }
        float mu = s * (1.0f / 192.0f);
        float var = s2 * (1.0f / 192.0f) - mu * mu;
        smu[tid] = mu;
        srstd[tid] = rsqrtf(var + 1e-5f);
    }
    __syncthreads();
    #pragma unroll
    for (int t = 0; t < 2; t++) {
        #pragma unroll
        for (int half = 0; half < 2; half++) {
            int row = wm + t * 16 + g + half * 8;
            int rowg = bm + row;
            int posr = rowg >= LTc ? rowg - LTc : rowg;
            float mu = smu[row], rs = srstd[row];
            float* wr = g_src + (size_t)rowg * DD;
            float* ws = g_srnd + (size_t)rowg * DD;
            float* wq = g_qrnd + (size_t)rowg * DD;
            const float* pp = g_pos + (size_t)posr * DD;
            #pragma unroll
            for (int u = 0; u < 6; u++) {
                int col = wn + u * 8 + tig * 2;
                float o0 = (acc[t][u][half * 2 + 0] - mu) * rs * gamma[col]     + beta[col];
                float o1 = (acc[t][u][half * 2 + 1] - mu) * rs * gamma[col + 1] + beta[col + 1];
                *reinterpret_cast<float2*>(&wr[col]) = make_float2(o0, o1);
                *reinterpret_cast<float2*>(&ws[col]) = make_float2(rnd(o0), rnd(o1));
                if (WRITEQ) {
                    *reinterpret_cast<float2*>(&wq[col]) =
                        make_float2(rnd(o0 + pp[col]), rnd(o1 + pp[col + 1]));
                }
            }
        }
    }
}

// ---------------- merged projection GEMM (all 4 segments, one launch) -------
__global__ __launch_bounds__(256) void k_projall(
    const float* __restrict__ feat0, const float* __restrict__ feat1,
    const float* __restrict__ pw0, const float* __restrict__ pb0,
    const float* __restrict__ pw1, const float* __restrict__ pb1)
{
    const int by = blockIdx.y;
    const float* A; float* Cb; int Mstr, bm;
    const float* Wt; const float* bias;
    if (by < 72)       { A = feat0;                       Cb = g_src;                          Mstr = N0c; Wt = pw0; bias = pb0; bm = by * 128; }
    else if (by < 90)  { A = feat1;                       Cb = g_src + (size_t)N0c * DD;       Mstr = N1c; Wt = pw1; bias = pb1; bm = (by - 72) * 128; }
    else if (by < 162) { A = feat0 + (size_t)DD * N0c;    Cb = g_src + (size_t)LTc * DD;       Mstr = N0c; Wt = pw0; bias = pb0; bm = (by - 90) * 128; }
    else               { A = feat1 + (size_t)DD * N1c;    Cb = g_src + (size_t)(LTc + N0c) * DD; Mstr = N1c; Wt = pw1; bias = pb1; bm = (by - 162) * 128; }

    __shared__ uint32_t As[2][16][132];
    __shared__ uint32_t Bs[2][16][68];
    const int bn = blockIdx.x * 64;
    const int tid = threadIdx.x;
    const int am = tid & 127, ak0 = tid >> 7;
    const int bk = tid & 15, bn0 = tid >> 4;
    const int warp = tid >> 5, lane = tid & 31;
    const int wm = (warp >> 1) * 32, wn = (warp & 1) * 32;
    const int g = lane >> 2, tig = lane & 3;
    const int K = DD;

    float acc[2][4][4];
    #pragma unroll
    for (int t = 0; t < 2; t++)
        #pragma unroll
        for (int u = 0; u < 4; u++)
            #pragma unroll
            for (int r = 0; r < 4; r++) acc[t][u][r] = 0.f;

    float ra[8], rb[4];
    #pragma unroll
    for (int r = 0; r < 8; r++) ra[r] = A[(size_t)(ak0 + 2 * r) * Mstr + bm + am];
    #pragma unroll
    for (int r = 0; r < 4; r++) rb[r] = Wt[(size_t)(bn + bn0 + 16 * r) * K + bk];
    #pragma unroll
    for (int r = 0; r < 8; r++) As[0][ak0 + 2 * r][am] = f2tf32(ra[r]);
    #pragma unroll
    for (int r = 0; r < 4; r++) Bs[0][bk][bn0 + 16 * r] = f2tf32(rb[r]);
    __syncthreads();

    const int niter = K / 16;
    int buf = 0;
    for (int it = 0; it < niter; it++) {
        const int k0 = (it + 1) * 16;
        const bool more = (it + 1 < niter);
        if (more) {
            #pragma unroll
            for (int r = 0; r < 8; r++) ra[r] = A[(size_t)(k0 + ak0 + 2 * r) * Mstr + bm + am];
            #pragma unroll
            for (int r = 0; r < 4; r++) rb[r] = Wt[(size_t)(bn + bn0 + 16 * r) * K + k0 + bk];
        }
        #pragma unroll
        for (int s = 0; s < 16; s += 8) {
            uint32_t af[2][4], bf[4][2];
            #pragma unroll
            for (int t = 0; t < 2; t++) {
                af[t][0] = As[buf][s + tig    ][wm + t * 16 + g];
                af[t][1] = As[buf][s + tig    ][wm + t * 16 + g + 8];
                af[t][2] = As[buf][s + tig + 4][wm + t * 16 + g];
                af[t][3] = As[buf][s + tig + 4][wm + t * 16 + g + 8];
            }
            #pragma unroll
            for (int u = 0; u < 4; u++) {
                bf[u][0] = Bs[buf][s + tig    ][wn + u * 8 + g];
                bf[u][1] = Bs[buf][s + tig + 4][wn + u * 8 + g];
            }
            #pragma unroll
            for (int t = 0; t < 2; t++)
                #pragma unroll
                for (int u = 0; u < 4; u++)
                    mma_tf32(acc[t][u], af[t], bf[u]);
        }
        if (more) {
            #pragma unroll
            for (int r = 0; r < 8; r++) As[buf ^ 1][ak0 + 2 * r][am] = f2tf32(ra[r]);
            #pragma unroll
            for (int r = 0; r < 4; r++) Bs[buf ^ 1][bk][bn0 + 16 * r] = f2tf32(rb[r]);
        }
        __syncthreads();
        buf ^= 1;
    }

    #pragma unroll
    for (int t = 0; t < 2; t++) {
        int row0 = bm + wm + t * 16 + g;
        int row1 = row0 + 8;
        #pragma unroll
        for (int u = 0; u < 4; u++) {
            int col = bn + wn + u * 8 + tig * 2;
            float b0 = bias[col], b1 = bias[col + 1];
            float2 v0 = make_float2(acc[t][u][0] + b0, acc[t][u][1] + b1);
            float2 v1 = make_float2(acc[t][u][2] + b0, acc[t][u][3] + b1);
            *reinterpret_cast<float2*>(&Cb[(size_t)row0 * DD + col]) = v0;
            *reinterpret_cast<float2*>(&Cb[(size_t)row1 * DD + col]) = v1;
        }
    }
}

// ---------------- GroupNorm stats: 512 blocks, deterministic partials -------
__global__ void k_gn_stats() {
    int blk = blockIdx.x;                 // lev*256 + b*128 + g*4 + chunk
    int chunk = blk & 3, g = (blk >> 2) & 31, b = (blk >> 7) & 1, lev = blk >> 8;
    int tokbase = lev ? N0c : 0;
    int ntok = lev ? N1c : N0c;
    int rows = ntok / 4;
    const float* base = g_src + (size_t)(b * LTc + tokbase + chunk * rows) * DD + g * 6;
    float s = 0.f, ss = 0.f;
    for (int r = threadIdx.x; r < rows; r += 256) {
        const float* p = base + (size_t)r * DD;
        float2 a = *reinterpret_cast<const float2*>(p);
        float2 c = *reinterpret_cast<const float2*>(p + 2);
        float2 e = *reinterpret_cast<const float2*>(p + 4);
        s  += a.x + a.y + c.x + c.y + e.x + e.y;
        ss += a.x * a.x + a.y * a.y + c.x * c.x + c.y * c.y + e.x * e.x + e.y * e.y;
    }
    #pragma unroll
    for (int o = 16; o; o >>= 1) {
        s  += __shfl_xor_sync(0xffffffffu, s, o);
        ss += __shfl_xor_sync(0xffffffffu, ss, o);
    }
    __shared__ float sh[16];
    int w = threadIdx.x >> 5, lane = threadIdx.x & 31;
    if (lane == 0) { sh[w] = s; sh[w + 8] = ss; }
    __syncthreads();
    if (threadIdx.x == 0) {
        float S = 0.f, SS = 0.f;
        for (int w2 = 0; w2 < 8; w2++) { S += sh[w2]; SS += sh[w2 + 8]; }
        g_ps[blk] = S;
        g_ps2[blk] = SS;
    }
}

// apply + produce rounded copies for layer-0 GEMM inputs
__global__ void k_gn_apply(const float* __restrict__ gg0, const float* __restrict__ gb0,
                           const float* __restrict__ gg1, const float* __restrict__ gb1) {
    int idx = blockIdx.x * blockDim.x + threadIdx.x;
    if (idx >= MT * DD) return;
    int c = idx % DD;
    int r = idx / DD;
    int b = r / LTc;
    int tok = r % LTc;
    int lev = tok >= N0c;
    const float* gg = lev ? gg1 : gg0;
    const float* gb = lev ? gb1 : gb0;
    int g = c / 6;
    int pbase = lev * 256 + b * 128 + g * 4;
    float S  = g_ps[pbase] + g_ps[pbase + 1] + g_ps[pbase + 2] + g_ps[pbase + 3];
    float SS = g_ps2[pbase] + g_ps2[pbase + 1] + g_ps2[pbase + 2] + g_ps2[pbase + 3];
    float inv = 1.0f / (float)((lev ? N1c : N0c) * 6);
    float mu = S * inv;
    float rstd = rsqrtf(SS * inv - mu * mu + 1e-5f);
    float x = g_src[idx];
    float y = (x - mu) * rstd * gg[c] + gb[c];
    g_src[idx] = y;
    g_srnd[idx] = rnd(y);
    g_qrnd[idx] = rnd(y + g_pos[(size_t)tok * DD + c]);
}

// ---------------- deformable attention gather (fp16 v, softmax fused) --------
__global__ __launch_bounds__(256) void k_deform() {
    int bq = blockIdx.x;
    int q = bq % LTc, b = bq / LTc;
    __shared__ float s_off[128];
    __shared__ float s_aw[64];
    int tid = threadIdx.x;
    size_t row = (size_t)(b * LTc + q);
    if (tid < 192) {
        float v = g_offaw[row * DD + tid];
        if (tid < 128) s_off[tid] = v;
        else           s_aw[tid - 128] = v;
    }
    float refx = g_ref[q * 2 + 0];
    float refy = g_ref[q * 2 + 1];
    __syncthreads();
    int h = tid >> 5, lane = tid & 31;

    float wv[8];
    float m = -1e30f;
    #pragma unroll
    for (int i = 0; i < 8; i++) { wv[i] = s_aw[h * 8 + i]; m = fmaxf(m, wv[i]); }
    float sum = 0.f;
    #pragma unroll
    for (int i = 0; i < 8; i++) { wv[i] = expf(wv[i] - m); sum += wv[i]; }
    float inv = 1.0f / sum;
    #pragma unroll
    for (int i = 0; i < 8; i++) wv[i] *= inv;

    float acc0 = 0.f, acc1 = 0.f;
    const __half* vb = g_vh + (size_t)b * LTc * DD + h * HDD + lane;
    #pragma unroll
    for (int l = 0; l < 2; l++) {
        const int Wl = l ? W1c : W0c;
        const int Hl = l ? H1c : H0c;
        const int st = l ? N0c : 0;
        const float fW = (float)Wl, fH = (float)Hl;
        #pragma unroll
        for (int p = 0; p < 4; p++) {
            float ox = s_off[h * 16 + l * 8 + p * 2 + 0];
            float oy = s_off[h * 16 + l * 8 + p * 2 + 1];
            float aww = wv[l * 4 + p];
            float x = (refx + ox / fW) * fW - 0.5f;
            float y = (refy + oy / fH) * fH - 0.5f;
            float x0 = floorf(x), y0 = floorf(y);
            float wx = x - x0, wy = y - y0;
            float cw[4] = { (1.f - wx) * (1.f - wy), wx * (1.f - wy),
                            (1.f - wx) * wy,         wx * wy };
            float cx[4] = { x0, x0 + 1.f, x0, x0 + 1.f };
            float cy[4] = { y0, y0, y0 + 1.f, y0 + 1.f };
            #pragma unroll
            for (int c4 = 0; c4 < 4; c4++) {
                bool valid = (cx[c4] >= 0.f) && (cx[c4] <= fW - 1.f) &&
                             (cy[c4] >= 0.f) && (cy[c4] <= fH - 1.f);
                if (valid && lane < HDD) {
                    int xi = (int)cx[c4], yi = (int)cy[c4];
                    float vload = __half2float(vb[(size_t)(st + yi * Wl + xi) * DD]);
                    if (c4 & 1) acc1 = fmaf(cw[c4] * aww, vload, acc1);
                    else        acc0 = fmaf(cw[c4] * aww, vload, acc0);
                }
            }
        }
    }
    if (lane < HDD) g_attn[row * DD + h * HDD + lane] = rnd(acc0 + acc1);
}

// ---------------- output transpose: both levels in ONE launch ---------------
__global__ void k_out(float* __restrict__ dst) {
    __shared__ float tile[32][33];
    int b = blockIdx.z;
    int bx = blockIdx.x;
    int tokbase, ntok;
    float* base;
    if (bx < N0c / 32) { tokbase = 0;   ntok = N0c; base = dst; }
    else               { tokbase = N0c; ntok = N1c; base = dst + (size_t)NB * DD * N0c; bx -= N0c / 32; }
    int tok0 = bx * 32, d0 = blockIdx.y * 32;
    int tx = threadIdx.x, ty = threadIdx.y;
    tile[ty][tx] = g_src[(size_t)(b * LTc + tokbase + tok0 + ty) * DD + d0 + tx];
    __syncthreads();
    base[(size_t)b * DD * ntok + (size_t)(d0 + ty) * ntok + tok0 + tx] = tile[tx][ty];
}

// ---------------- host orchestration ----------------
extern "C" void kernel_launch(void* const* d_in, const int* in_sizes, int n_in,
                              void* d_out, int out_size) {
    const float* feat0      = (const float*)d_in[0];
    const float* feat1      = (const float*)d_in[1];
    const float* proj_w0    = (const float*)d_in[3];
    const float* proj_b0    = (const float*)d_in[4];
    const float* gn_g0      = (const float*)d_in[5];
    const float* gn_b0      = (const float*)d_in[6];
    const float* proj_w1    = (const float*)d_in[7];
    const float* proj_b1    = (const float*)d_in[8];
    const float* gn_g1      = (const float*)d_in[9];
    const float* gn_b1      = (const float*)d_in[10];
    const float* level_emb  = (const float*)d_in[11];
    const float* so_W       = (const float*)d_in[12];
    const float* so_b       = (const float*)d_in[13];
    const float* aw_W       = (const float*)d_in[14];
    const float* aw_b       = (const float*)d_in[15];
    const float* vp_W       = (const float*)d_in[16];
    const float* vp_b       = (const float*)d_in[17];
    const float* op_W       = (const float*)d_in[18];
    const float* op_b       = (const float*)d_in[19];
    const float* ln1_g      = (const float*)d_in[20];
    const float* ln1_b      = (const float*)d_in[21];
    const float* l1_W       = (const float*)d_in[22];
    const float* l1_b       = (const float*)d_in[23];
    const float* l2_W       = (const float*)d_in[24];
    const float* l2_b       = (const float*)d_in[25];
    const float* ln2_g      = (const float*)d_in[26];
    const float* ln2_b      = (const float*)d_in[27];

    float *p_qrnd, *p_srnd, *p_offaw, *p_attn, *p_ffn;
    float *p_wcomb, *p_bcomb, *p_wv, *p_wo, *p_w1, *p_w2;
    cudaGetSymbolAddress((void**)&p_qrnd,  g_qrnd);
    cudaGetSymbolAddress((void**)&p_srnd,  g_srnd);
    cudaGetSymbolAddress((void**)&p_offaw, g_offaw);
    cudaGetSymbolAddress((void**)&p_attn,  g_attn);
    cudaGetSymbolAddress((void**)&p_ffn,   g_ffn);
    cudaGetSymbolAddress((void**)&p_wcomb, g_wcomb);
    cudaGetSymbolAddress((void**)&p_bcomb, g_bcomb);
    cudaGetSymbolAddress((void**)&p_wv,    g_wv);
    cudaGetSymbolAddress((void**)&p_wo,    g_wo);
    cudaGetSymbolAddress((void**)&p_w1,    g_w1);
    cudaGetSymbolAddress((void**)&p_w2,    g_w2);

    cudaFuncSetAttribute(k_gemm_ln<false>, cudaFuncAttributeMaxDynamicSharedMemorySize, LN_SMEM);
    cudaFuncSetAttribute(k_gemm_ln<true>,  cudaFuncAttributeMaxDynamicSharedMemorySize, LN_SMEM);

    // prelude (4 launches)
    k_init<<<(LTc * DD + 255) / 256, 256>>>(so_W, so_b, aw_W, aw_b, vp_W, op_W, l1_W, l2_W, level_emb);
    k_projall<<<dim3(DD / 64, 180), 256>>>(feat0, feat1, proj_w0, proj_b0, proj_w1, proj_b1);
    k_gn_stats<<<512, 256>>>();
    k_gn_apply<<<(MT * DD + 255) / 256, 256>>>(gn_g0, gn_b0, gn_g1, gn_b1);

    // encoder layers (5 launches each)
    for (int i = 0; i < NLAY; i++) {
        k_gemm_dual<<<dim3(3, MT / 64, 2), 128>>>(
            p_qrnd, p_wcomb + (size_t)i * DD * DD, p_bcomb + (size_t)i * DD, p_offaw,
            p_srnd, p_wv + (size_t)i * DD * DD, vp_b + (size_t)i * DD);
        k_deform<<<MT, 256>>>();
        k_gemm_ln<false><<<MT / 64, 256, LN_SMEM>>>(
            p_attn, p_wo + (size_t)i * DD * DD, op_b + (size_t)i * DD,
            ln1_g + (size_t)i * DD, ln1_b + (size_t)i * DD, DD);
        k_gemm_main<true, true><<<dim3(4, MT / 64), 128>>>(
            p_srnd, p_w1 + (size_t)i * DD * FFc, l1_b + (size_t)i * FFc, p_ffn, FFc, DD);
        k_gemm_ln<true><<<MT / 64, 256, LN_SMEM>>>(
            p_ffn, p_w2 + (size_t)i * FFc * DD, l2_b + (size_t)i * DD,
            ln2_g + (size_t)i * DD, ln2_b + (size_t)i * DD, FFc);
    }

    // outputs: m0 then m1, each (B, D, H, W) — single launch
    k_out<<<dim3(N0c / 32 + N1c / 32, DD / 32, NB), dim3(32, 32)>>>((float*)d_out);
}

// round 14
// speedup vs baseline: 1.1979x; 1.1979x over previous
#include <cuda_runtime.h>
#include <math.h>
#include <stdint.h>

// ---------------- problem constants ----------------
#define NB   2
#define DD   192
#define NHH  8
#define HDD  24
#define H0c  96
#define W0c  96
#define H1c  48
#define W1c  48
#define N0c  (H0c*W0c)      // 9216
#define N1c  (H1c*W1c)      // 2304
#define LTc  (N0c+N1c)      // 11520
#define MT   (NB*LTc)       // 23040
#define FFc  256
#define NLAY 6

#define LN_SMEM (15360 + 38400)   // dynamic smem for k_gemm_ln (3-stage)

// ---------------- device scratch ----------------
__device__ float  g_src  [MT*DD];      // running activation (fp32 exact trunk)
__device__ float  g_srnd [MT*DD];      // rna(src)  — GEMM A input
__device__ float  g_qrnd [MT*DD];      // rna(src+pos) — GEMM A input
__device__ float  g_pos  [LTc*DD];
__device__ float  g_ref  [LTc*2];
__device__ float  g_offaw[MT*DD];      // offsets(128) + aw logits(64)
__device__ float  g_v    [MT*DD];      // value projection (fp32)
__device__ float  g_attn [MT*DD];      // rna-rounded
__device__ float  g_ffn  [MT*FFc];     // rna-rounded
__device__ float  g_wcomb[NLAY*DD*DD]; // rna(so_W || aw_W)
__device__ float  g_bcomb[NLAY*DD];
__device__ float  g_wv   [NLAY*DD*DD];
__device__ float  g_wo   [NLAY*DD*DD];
__device__ float  g_w1   [NLAY*DD*FFc];
__device__ float  g_w2   [NLAY*FFc*DD];
__device__ float  g_ps   [512];        // GN partial sums
__device__ float  g_ps2  [512];        // GN partial sumsq

// ---------------- helpers ----------------
__device__ __forceinline__ uint32_t f2tf32(float x) {
    uint32_t r;
    asm("cvt.rna.tf32.f32 %0, %1;" : "=r"(r) : "f"(x));
    return r;
}
__device__ __forceinline__ float rnd(float x) { return __uint_as_float(f2tf32(x)); }

__device__ __forceinline__ void mma_tf32(float* c, const uint32_t* a, const uint32_t* b) {
    asm volatile(
        "mma.sync.aligned.m16n8k8.row.col.f32.tf32.tf32.f32 "
        "{%0,%1,%2,%3}, {%4,%5,%6,%7}, {%8,%9}, {%0,%1,%2,%3};"
        : "+f"(c[0]), "+f"(c[1]), "+f"(c[2]), "+f"(c[3])
        : "r"(a[0]), "r"(a[1]), "r"(a[2]), "r"(a[3]), "r"(b[0]), "r"(b[1]));
}
__device__ __forceinline__ uint32_t s2u(const void* p) {
    return (uint32_t)__cvta_generic_to_shared(p);
}
__device__ __forceinline__ void cp16(uint32_t dst, const void* src) {
    asm volatile("cp.async.cg.shared.global [%0], [%1], 16;" :: "r"(dst), "l"(src));
}
__device__ __forceinline__ void cp_commit() { asm volatile("cp.async.commit_group;"); }
template<int W> __device__ __forceinline__ void cp_wait() {
    asm volatile("cp.async.wait_group %0;" :: "n"(W));
}

// ---------------- fused init: weight prep + pos embed + ref pts (ONE launch) -
__global__ void k_init(const float* __restrict__ soW, const float* __restrict__ sob,
                       const float* __restrict__ awW, const float* __restrict__ awb,
                       const float* __restrict__ vpW, const float* __restrict__ opW,
                       const float* __restrict__ l1W, const float* __restrict__ l2W,
                       const float* __restrict__ level_embed) {
    int idx = blockIdx.x * blockDim.x + threadIdx.x;
    const int SZ1 = NLAY * DD * DD;
    const int SZ2 = NLAY * DD * FFc;
    if (idx < SZ1) {
        int i = idx / (DD * DD);
        int rem = idx % (DD * DD);
        int k = rem / DD, n = rem % DD;
        float w = (n < 128) ? soW[(size_t)i * DD * 128 + k * 128 + n]
                            : awW[(size_t)i * DD * 64 + k * 64 + (n - 128)];
        g_wcomb[idx] = rnd(w);
        g_wv[idx] = rnd(vpW[idx]);
        g_wo[idx] = rnd(opW[idx]);
    }
    if (idx < SZ2) {
        g_w1[idx] = rnd(l1W[idx]);
        g_w2[idx] = rnd(l2W[idx]);
    }
    if (idx < NLAY * DD) {
        int i = idx / DD, n = idx % DD;
        g_bcomb[idx] = (n < 128) ? sob[i * 128 + n] : awb[i * 64 + (n - 128)];
    }
    if (idx < LTc * DD) {
        int l = idx / DD, d = idx % DD;
        int lev, i, j, Hc, Wc;
        if (l < N0c) { lev = 0; i = l / W0c; j = l % W0c; Hc = H0c; Wc = W0c; }
        else         { lev = 1; int ll = l - N0c; i = ll / W1c; j = ll % W1c; Hc = H1c; Wc = W1c; }
        const float TWO_PI = 6.283185307179586f;
        float v; int dd;
        if (d < 96) { v = ((float)i + 0.5f) / ((float)Hc + 1e-6f) * TWO_PI; dd = d; }
        else        { v = ((float)j + 0.5f) / ((float)Wc + 1e-6f) * TWO_PI; dd = d - 96; }
        float e = (float)(2 * (dd >> 1)) / 96.0f;
        float t = v / powf(10000.0f, e);
        float val = (dd & 1) ? cosf(t) : sinf(t);
        g_pos[idx] = val + level_embed[lev * DD + d];
        if (d == 0) {
            g_ref[l * 2 + 0] = ((float)j + 0.5f) / (float)Wc;
            g_ref[l * 2 + 1] = ((float)i + 0.5f) / (float)Hc;
        }
    }
}

// ---------------- main TF32 GEMM: BM=64, BN=64, 128 thr, 3-stage cp.async ----
template <bool RELU, bool ROUND>
__global__ __launch_bounds__(128) void k_gemm_main(
    const float* __restrict__ A, const float* __restrict__ Bm,
    const float* __restrict__ bias, float* __restrict__ C,
    int N, int K)
{
    __shared__ float As[3][64][20];
    __shared__ float Bs[3][16][72];
    const int bm = blockIdx.y * 64, bn = blockIdx.x * 64;
    const int tid = threadIdx.x;
    const int warp = tid >> 5, lane = tid & 31;
    const int wm = (warp >> 1) * 32, wn = (warp & 1) * 32;
    const int g = lane >> 2, tig = lane & 3;
    const float* Ag = A + (size_t)bm * K;

    float acc[2][4][4];
    #pragma unroll
    for (int t = 0; t < 2; t++)
        #pragma unroll
        for (int u = 0; u < 4; u++)
            #pragma unroll
            for (int r = 0; r < 4; r++) acc[t][u][r] = 0.f;

    const int mA = tid >> 2, cA = (tid & 3) * 4;
    const int kB = tid >> 4, cB = (tid & 15) * 4;

    auto load_stage = [&](int st, int kk) {
        cp16(s2u(&As[st][mA][cA]),      Ag + (size_t)mA * K + kk + cA);
        cp16(s2u(&As[st][mA + 32][cA]), Ag + (size_t)(mA + 32) * K + kk + cA);
        cp16(s2u(&Bs[st][kB][cB]),      Bm + (size_t)(kk + kB) * N + bn + cB);
        cp16(s2u(&Bs[st][kB + 8][cB]),  Bm + (size_t)(kk + kB + 8) * N + bn + cB);
    };

    const int niter = K / 16;
    load_stage(0, 0);  cp_commit();
    load_stage(1, 16); cp_commit();
    cp_wait<1>();
    __syncthreads();

    for (int it = 0; it < niter; it++) {
        if (it + 2 < niter) load_stage((it + 2) % 3, (it + 2) * 16);
        cp_commit();
        const int buf = it % 3;
        #pragma unroll
        for (int s = 0; s < 16; s += 8) {
            uint32_t af[2][4], bf[4][2];
            #pragma unroll
            for (int t = 0; t < 2; t++) {
                af[t][0] = __float_as_uint(As[buf][wm + t * 16 + g    ][s + tig]);
                af[t][1] = __float_as_uint(As[buf][wm + t * 16 + g + 8][s + tig]);
                af[t][2] = __float_as_uint(As[buf][wm + t * 16 + g    ][s + tig + 4]);
                af[t][3] = __float_as_uint(As[buf][wm + t * 16 + g + 8][s + tig + 4]);
            }
            #pragma unroll
            for (int u = 0; u < 4; u++) {
                bf[u][0] = __float_as_uint(Bs[buf][s + tig    ][wn + u * 8 + g]);
                bf[u][1] = __float_as_uint(Bs[buf][s + tig + 4][wn + u * 8 + g]);
            }
            #pragma unroll
            for (int t = 0; t < 2; t++)
                #pragma unroll
                for (int u = 0; u < 4; u++)
                    mma_tf32(acc[t][u], af[t], bf[u]);
        }
        cp_wait<1>();
        __syncthreads();
    }

    #pragma unroll
    for (int t = 0; t < 2; t++) {
        int row0 = bm + wm + t * 16 + g;
        int row1 = row0 + 8;
        #pragma unroll
        for (int u = 0; u < 4; u++) {
            int col = bn + wn + u * 8 + tig * 2;
            float b0 = bias[col], b1 = bias[col + 1];
            float2 v0 = make_float2(acc[t][u][0] + b0, acc[t][u][1] + b1);
            float2 v1 = make_float2(acc[t][u][2] + b0, acc[t][u][3] + b1);
            if (RELU) {
                v0.x = fmaxf(v0.x, 0.f); v0.y = fmaxf(v0.y, 0.f);
                v1.x = fmaxf(v1.x, 0.f); v1.y = fmaxf(v1.y, 0.f);
            }
            if (ROUND) {
                v0.x = rnd(v0.x); v0.y = rnd(v0.y);
                v1.x = rnd(v1.x); v1.y = rnd(v1.y);
            }
            *reinterpret_cast<float2*>(&C[(size_t)row0 * N + col]) = v0;
            *reinterpret_cast<float2*>(&C[(size_t)row1 * N + col]) = v1;
        }
    }
}

// ---------------- dual GEMM: offaw (z=0) and v (z=1) in one launch ----------
__global__ __launch_bounds__(128) void k_gemm_dual(
    const float* __restrict__ A0, const float* __restrict__ B0,
    const float* __restrict__ b0p, float* __restrict__ C0,
    const float* __restrict__ A1, const float* __restrict__ B1,
    const float* __restrict__ b1p, float* __restrict__ C1)
{
    const float* A  = blockIdx.z ? A1 : A0;
    const float* Bm = blockIdx.z ? B1 : B0;
    const float* bias = blockIdx.z ? b1p : b0p;
    float* C = blockIdx.z ? C1 : C0;
    const int N = DD, K = DD;

    __shared__ float As[3][64][20];
    __shared__ float Bs[3][16][72];
    const int bm = blockIdx.y * 64, bn = blockIdx.x * 64;
    const int tid = threadIdx.x;
    const int warp = tid >> 5, lane = tid & 31;
    const int wm = (warp >> 1) * 32, wn = (warp & 1) * 32;
    const int g = lane >> 2, tig = lane & 3;
    const float* Ag = A + (size_t)bm * K;

    float acc[2][4][4];
    #pragma unroll
    for (int t = 0; t < 2; t++)
        #pragma unroll
        for (int u = 0; u < 4; u++)
            #pragma unroll
            for (int r = 0; r < 4; r++) acc[t][u][r] = 0.f;

    const int mA = tid >> 2, cA = (tid & 3) * 4;
    const int kB = tid >> 4, cB = (tid & 15) * 4;

    auto load_stage = [&](int st, int kk) {
        cp16(s2u(&As[st][mA][cA]),      Ag + (size_t)mA * K + kk + cA);
        cp16(s2u(&As[st][mA + 32][cA]), Ag + (size_t)(mA + 32) * K + kk + cA);
        cp16(s2u(&Bs[st][kB][cB]),      Bm + (size_t)(kk + kB) * N + bn + cB);
        cp16(s2u(&Bs[st][kB + 8][cB]),  Bm + (size_t)(kk + kB + 8) * N + bn + cB);
    };

    const int niter = K / 16;
    load_stage(0, 0);  cp_commit();
    load_stage(1, 16); cp_commit();
    cp_wait<1>();
    __syncthreads();

    for (int it = 0; it < niter; it++) {
        if (it + 2 < niter) load_stage((it + 2) % 3, (it + 2) * 16);
        cp_commit();
        const int buf = it % 3;
        #pragma unroll
        for (int s = 0; s < 16; s += 8) {
            uint32_t af[2][4], bf[4][2];
            #pragma unroll
            for (int t = 0; t < 2; t++) {
                af[t][0] = __float_as_uint(As[buf][wm + t * 16 + g    ][s + tig]);
                af[t][1] = __float_as_uint(As[buf][wm + t * 16 + g + 8][s + tig]);
                af[t][2] = __float_as_uint(As[buf][wm + t * 16 + g    ][s + tig + 4]);
                af[t][3] = __float_as_uint(As[buf][wm + t * 16 + g + 8][s + tig + 4]);
            }
            #pragma unroll
            for (int u = 0; u < 4; u++) {
                bf[u][0] = __float_as_uint(Bs[buf][s + tig    ][wn + u * 8 + g]);
                bf[u][1] = __float_as_uint(Bs[buf][s + tig + 4][wn + u * 8 + g]);
            }
            #pragma unroll
            for (int t = 0; t < 2; t++)
                #pragma unroll
                for (int u = 0; u < 4; u++)
                    mma_tf32(acc[t][u], af[t], bf[u]);
        }
        cp_wait<1>();
        __syncthreads();
    }

    #pragma unroll
    for (int t = 0; t < 2; t++) {
        int row0 = bm + wm + t * 16 + g;
        int row1 = row0 + 8;
        #pragma unroll
        for (int u = 0; u < 4; u++) {
            int col = bn + wn + u * 8 + tig * 2;
            float b0 = bias[col], b1 = bias[col + 1];
            float2 v0 = make_float2(acc[t][u][0] + b0, acc[t][u][1] + b1);
            float2 v1 = make_float2(acc[t][u][2] + b0, acc[t][u][3] + b1);
            *reinterpret_cast<float2*>(&C[(size_t)row0 * N + col]) = v0;
            *reinterpret_cast<float2*>(&C[(size_t)row1 * N + col]) = v1;
        }
    }
}

// ---------------- TF32 GEMM + residual + LayerNorm, 3-stage cp.async --------
template <bool WRITEQ>
__global__ __launch_bounds__(256) void k_gemm_ln(
    const float* __restrict__ A, const float* __restrict__ Bm,
    const float* __restrict__ bias,
    const float* __restrict__ gamma, const float* __restrict__ beta,
    int K)
{
    extern __shared__ __align__(16) char sbuf[];
    float (*As)[64][20]  = reinterpret_cast<float(*)[64][20]>(sbuf);
    float (*Bs)[16][200] = reinterpret_cast<float(*)[16][200]>(sbuf + 15360);

    const int bm = blockIdx.x * 64;
    const int tid = threadIdx.x;
    const int warp = tid >> 5, lane = tid & 31;
    const int wm = (warp >> 2) * 32, wn = (warp & 3) * 48;
    const int g = lane >> 2, tig = lane & 3;
    const float* Ag = A + (size_t)bm * K;

    float acc[2][6][4];
    #pragma unroll
    for (int t = 0; t < 2; t++)
        #pragma unroll
        for (int u = 0; u < 6; u++)
            #pragma unroll
            for (int r = 0; r < 4; r++) acc[t][u][r] = 0.f;

    const int mA = tid >> 2, cA = (tid & 3) * 4;

    auto load_stage = [&](int st, int kk) {
        cp16(s2u(&As[st][mA][cA]), Ag + (size_t)mA * K + kk + cA);
        #pragma unroll
        for (int j = 0; j < 3; j++) {
            int idx = tid + j * 256;
            int k = idx / 48, n4 = (idx % 48) * 4;
            cp16(s2u(&Bs[st][k][n4]), Bm + (size_t)(kk + k) * DD + n4);
        }
    };

    const int niter = K / 16;
    load_stage(0, 0);  cp_commit();
    load_stage(1, 16); cp_commit();
    cp_wait<1>();
    __syncthreads();

    for (int it = 0; it < niter; it++) {
        if (it + 2 < niter) load_stage((it + 2) % 3, (it + 2) * 16);
        cp_commit();
        const int buf = it % 3;
        #pragma unroll
        for (int s = 0; s < 16; s += 8) {
            uint32_t af[2][4], bf[6][2];
            #pragma unroll
            for (int t = 0; t < 2; t++) {
                af[t][0] = __float_as_uint(As[buf][wm + t * 16 + g    ][s + tig]);
                af[t][1] = __float_as_uint(As[buf][wm + t * 16 + g + 8][s + tig]);
                af[t][2] = __float_as_uint(As[buf][wm + t * 16 + g    ][s + tig + 4]);
                af[t][3] = __float_as_uint(As[buf][wm + t * 16 + g + 8][s + tig + 4]);
            }
            #pragma unroll
            for (int u = 0; u < 6; u++) {
                bf[u][0] = __float_as_uint(Bs[buf][s + tig    ][wn + u * 8 + g]);
                bf[u][1] = __float_as_uint(Bs[buf][s + tig + 4][wn + u * 8 + g]);
            }
            #pragma unroll
            for (int t = 0; t < 2; t++)
                #pragma unroll
                for (int u = 0; u < 6; u++)
                    mma_tf32(acc[t][u], af[t], bf[u]);
        }
        cp_wait<1>();
        __syncthreads();
    }

    // ---- fused epilogue: x = acc + bias + res; LayerNorm per row ----
    float* psum  = reinterpret_cast<float*>(sbuf);   // [64][18]
    float* psum2 = psum + 64 * 18;                   // [64][18]
    float* smu   = psum2 + 64 * 18;                  // [64]
    float* srstd = smu + 64;                         // [64]
    const int widx = (warp & 3) * 4 + tig;

    #pragma unroll
    for (int t = 0; t < 2; t++) {
        #pragma unroll
        for (int half = 0; half < 2; half++) {
            int row = wm + t * 16 + g + half * 8;
            const float* rr = g_src + (size_t)(bm + row) * DD;
            float s = 0.f, s2 = 0.f;
            #pragma unroll
            for (int u = 0; u < 6; u++) {
                int col = wn + u * 8 + tig * 2;
                float2 rv = *reinterpret_cast<const float2*>(&rr[col]);
                float x0 = acc[t][u][half * 2 + 0] + bias[col]     + rv.x;
                float x1 = acc[t][u][half * 2 + 1] + bias[col + 1] + rv.y;
                acc[t][u][half * 2 + 0] = x0;
                acc[t][u][half * 2 + 1] = x1;
                s += x0 + x1;
                s2 += x0 * x0 + x1 * x1;
            }
            psum [row * 18 + widx] = s;
            psum2[row * 18 + widx] = s2;
        }
    }
    __syncthreads();
    if (tid < 64) {
        float s = 0.f, s2 = 0.f;
        #pragma unroll
        for (int j = 0; j < 16; j++) { s += psum[tid * 18 + j]; s2 += psum2[tid * 18 + j]; }
        float mu = s * (1.0f / 192.0f);
        float var = s2 * (1.0f / 192.0f) - mu * mu;
        smu[tid] = mu;
        srstd[tid] = rsqrtf(var + 1e-5f);
    }
    __syncthreads();
    #pragma unroll
    for (int t = 0; t < 2; t++) {
        #pragma unroll
        for (int half = 0; half < 2; half++) {
            int row = wm + t * 16 + g + half * 8;
            int rowg = bm + row;
            int posr = rowg >= LTc ? rowg - LTc : rowg;
            float mu = smu[row], rs = srstd[row];
            float* wr = g_src + (size_t)rowg * DD;
            float* ws = g_srnd + (size_t)rowg * DD;
            float* wq = g_qrnd + (size_t)rowg * DD;
            const float* pp = g_pos + (size_t)posr * DD;
            #pragma unroll
            for (int u = 0; u < 6; u++) {
                int col = wn + u * 8 + tig * 2;
                float o0 = (acc[t][u][half * 2 + 0] - mu) * rs * gamma[col]     + beta[col];
                float o1 = (acc[t][u][half * 2 + 1] - mu) * rs * gamma[col + 1] + beta[col + 1];
                *reinterpret_cast<float2*>(&wr[col]) = make_float2(o0, o1);
                *reinterpret_cast<float2*>(&ws[col]) = make_float2(rnd(o0), rnd(o1));
                if (WRITEQ) {
                    *reinterpret_cast<float2*>(&wq[col]) =
                        make_float2(rnd(o0 + pp[col]), rnd(o1 + pp[col + 1]));
                }
            }
        }
    }
}

// ---------------- merged projection GEMM (all 4 segments, one launch) -------
__global__ __launch_bounds__(256) void k_projall(
    const float* __restrict__ feat0, const float* __restrict__ feat1,
    const float* __restrict__ pw0, const float* __restrict__ pb0,
    const float* __restrict__ pw1, const float* __restrict__ pb1)
{
    const int by = blockIdx.y;
    const float* A; float* Cb; int Mstr, bm;
    const float* Wt; const float* bias;
    if (by < 72)       { A = feat0;                       Cb = g_src;                          Mstr = N0c; Wt = pw0; bias = pb0; bm = by * 128; }
    else if (by < 90)  { A = feat1;                       Cb = g_src + (size_t)N0c * DD;       Mstr = N1c; Wt = pw1; bias = pb1; bm = (by - 72) * 128; }
    else if (by < 162) { A = feat0 + (size_t)DD * N0c;    Cb = g_src + (size_t)LTc * DD;       Mstr = N0c; Wt = pw0; bias = pb0; bm = (by - 90) * 128; }
    else               { A = feat1 + (size_t)DD * N1c;    Cb = g_src + (size_t)(LTc + N0c) * DD; Mstr = N1c; Wt = pw1; bias = pb1; bm = (by - 162) * 128; }

    __shared__ uint32_t As[2][16][132];
    __shared__ uint32_t Bs[2][16][68];
    const int bn = blockIdx.x * 64;
    const int tid = threadIdx.x;
    const int am = tid & 127, ak0 = tid >> 7;
    const int bk = tid & 15, bn0 = tid >> 4;
    const int warp = tid >> 5, lane = tid & 31;
    const int wm = (warp >> 1) * 32, wn = (warp & 1) * 32;
    const int g = lane >> 2, tig = lane & 3;
    const int K = DD;

    float acc[2][4][4];
    #pragma unroll
    for (int t = 0; t < 2; t++)
        #pragma unroll
        for (int u = 0; u < 4; u++)
            #pragma unroll
            for (int r = 0; r < 4; r++) acc[t][u][r] = 0.f;

    float ra[8], rb[4];
    #pragma unroll
    for (int r = 0; r < 8; r++) ra[r] = A[(size_t)(ak0 + 2 * r) * Mstr + bm + am];
    #pragma unroll
    for (int r = 0; r < 4; r++) rb[r] = Wt[(size_t)(bn + bn0 + 16 * r) * K + bk];
    #pragma unroll
    for (int r = 0; r < 8; r++) As[0][ak0 + 2 * r][am] = f2tf32(ra[r]);
    #pragma unroll
    for (int r = 0; r < 4; r++) Bs[0][bk][bn0 + 16 * r] = f2tf32(rb[r]);
    __syncthreads();

    const int niter = K / 16;
    int buf = 0;
    for (int it = 0; it < niter; it++) {
        const int k0 = (it + 1) * 16;
        const bool more = (it + 1 < niter);
        if (more) {
            #pragma unroll
            for (int r = 0; r < 8; r++) ra[r] = A[(size_t)(k0 + ak0 + 2 * r) * Mstr + bm + am];
            #pragma unroll
            for (int r = 0; r < 4; r++) rb[r] = Wt[(size_t)(bn + bn0 + 16 * r) * K + k0 + bk];
        }
        #pragma unroll
        for (int s = 0; s < 16; s += 8) {
            uint32_t af[2][4], bf[4][2];
            #pragma unroll
            for (int t = 0; t < 2; t++) {
                af[t][0] = As[buf][s + tig    ][wm + t * 16 + g];
                af[t][1] = As[buf][s + tig    ][wm + t * 16 + g + 8];
                af[t][2] = As[buf][s + tig + 4][wm + t * 16 + g];
                af[t][3] = As[buf][s + tig + 4][wm + t * 16 + g + 8];
            }
            #pragma unroll
            for (int u = 0; u < 4; u++) {
                bf[u][0] = Bs[buf][s + tig    ][wn + u * 8 + g];
                bf[u][1] = Bs[buf][s + tig + 4][wn + u * 8 + g];
            }
            #pragma unroll
            for (int t = 0; t < 2; t++)
                #pragma unroll
                for (int u = 0; u < 4; u++)
                    mma_tf32(acc[t][u], af[t], bf[u]);
        }
        if (more) {
            #pragma unroll
            for (int r = 0; r < 8; r++) As[buf ^ 1][ak0 + 2 * r][am] = f2tf32(ra[r]);
            #pragma unroll
            for (int r = 0; r < 4; r++) Bs[buf ^ 1][bk][bn0 + 16 * r] = f2tf32(rb[r]);
        }
        __syncthreads();
        buf ^= 1;
    }

    #pragma unroll
    for (int t = 0; t < 2; t++) {
        int row0 = bm + wm + t * 16 + g;
        int row1 = row0 + 8;
        #pragma unroll
        for (int u = 0; u < 4; u++) {
            int col = bn + wn + u * 8 + tig * 2;
            float b0 = bias[col], b1 = bias[col + 1];
            float2 v0 = make_float2(acc[t][u][0] + b0, acc[t][u][1] + b1);
            float2 v1 = make_float2(acc[t][u][2] + b0, acc[t][u][3] + b1);
            *reinterpret_cast<float2*>(&Cb[(size_t)row0 * DD + col]) = v0;
            *reinterpret_cast<float2*>(&Cb[(size_t)row1 * DD + col]) = v1;
        }
    }
}

// ---------------- GroupNorm stats: 512 blocks, deterministic partials -------
__global__ void k_gn_stats() {
    int blk = blockIdx.x;                 // lev*256 + b*128 + g*4 + chunk
    int chunk = blk & 3, g = (blk >> 2) & 31, b = (blk >> 7) & 1, lev = blk >> 8;
    int tokbase = lev ? N0c : 0;
    int ntok = lev ? N1c : N0c;
    int rows = ntok / 4;
    const float* base = g_src + (size_t)(b * LTc + tokbase + chunk * rows) * DD + g * 6;
    float s = 0.f, ss = 0.f;
    for (int r = threadIdx.x; r < rows; r += 256) {
        const float* p = base + (size_t)r * DD;
        float2 a = *reinterpret_cast<const float2*>(p);
        float2 c = *reinterpret_cast<const float2*>(p + 2);
        float2 e = *reinterpret_cast<const float2*>(p + 4);
        s  += a.x + a.y + c.x + c.y + e.x + e.y;
        ss += a.x * a.x + a.y * a.y + c.x * c.x + c.y * c.y + e.x * e.x + e.y * e.y;
    }
    #pragma unroll
    for (int o = 16; o; o >>= 1) {
        s  += __shfl_xor_sync(0xffffffffu, s, o);
        ss += __shfl_xor_sync(0xffffffffu, ss, o);
    }
    __shared__ float sh[16];
    int w = threadIdx.x >> 5, lane = threadIdx.x & 31;
    if (lane == 0) { sh[w] = s; sh[w + 8] = ss; }
    __syncthreads();
    if (threadIdx.x == 0) {
        float S = 0.f, SS = 0.f;
        for (int w2 = 0; w2 < 8; w2++) { S += sh[w2]; SS += sh[w2 + 8]; }
        g_ps[blk] = S;
        g_ps2[blk] = SS;
    }
}

// apply + produce rounded copies for layer-0 GEMM inputs
__global__ void k_gn_apply(const float* __restrict__ gg0, const float* __restrict__ gb0,
                           const float* __restrict__ gg1, const float* __restrict__ gb1) {
    int idx = blockIdx.x * blockDim.x + threadIdx.x;
    if (idx >= MT * DD) return;
    int c = idx % DD;
    int r = idx / DD;
    int b = r / LTc;
    int tok = r % LTc;
    int lev = tok >= N0c;
    const float* gg = lev ? gg1 : gg0;
    const float* gb = lev ? gb1 : gb0;
    int g = c / 6;
    int pbase = lev * 256 + b * 128 + g * 4;
    float S  = g_ps[pbase] + g_ps[pbase + 1] + g_ps[pbase + 2] + g_ps[pbase + 3];
    float SS = g_ps2[pbase] + g_ps2[pbase + 1] + g_ps2[pbase + 2] + g_ps2[pbase + 3];
    float inv = 1.0f / (float)((lev ? N1c : N0c) * 6);
    float mu = S * inv;
    float rstd = rsqrtf(SS * inv - mu * mu + 1e-5f);
    float x = g_src[idx];
    float y = (x - mu) * rstd * gg[c] + gb[c];
    g_src[idx] = y;
    g_srnd[idx] = rnd(y);
    g_qrnd[idx] = rnd(y + g_pos[(size_t)tok * DD + c]);
}

// ---------------- deformable attention: vectorized gather -------------------
// One (b,token) per block; warp = head. Lane layout: corner = lane/6 (0..3),
// quad = lane%6 (channels quad*4..quad*4+3). One LDG.128 covers all 4 corners
// of one sampling point (24 active lanes) -> 8 wide loads per (token,head)
// instead of 32 scalar loads. Corner partials reduced via shfl at the end.
__global__ __launch_bounds__(256) void k_deform() {
    int bq = blockIdx.x;
    int q = bq % LTc, b = bq / LTc;
    __shared__ float s_off[128];
    __shared__ float s_aw[64];
    int tid = threadIdx.x;
    size_t row = (size_t)(b * LTc + q);
    if (tid < 192) {
        float v = g_offaw[row * DD + tid];
        if (tid < 128) s_off[tid] = v;
        else           s_aw[tid - 128] = v;
    }
    float refx = g_ref[q * 2 + 0];
    float refy = g_ref[q * 2 + 1];
    __syncthreads();
    const int h = tid >> 5, lane = tid & 31;
    const int corner = lane / 6;          // 0..3 active, 4..5 idle
    const int cq = lane - corner * 6;     // channel quad 0..5
    const bool active = lane < 24;
    const float cxoff = (float)(corner & 1);
    const float cyoff = (float)((corner >> 1) & 1);

    // softmax over this head's 8 logits (redundant per lane)
    float wv[8];
    float m = -1e30f;
    #pragma unroll
    for (int i = 0; i < 8; i++) { wv[i] = s_aw[h * 8 + i]; m = fmaxf(m, wv[i]); }
    float sum = 0.f;
    #pragma unroll
    for (int i = 0; i < 8; i++) { wv[i] = __expf(wv[i] - m); sum += wv[i]; }
    float inv = 1.0f / sum;

    float4 acc = make_float4(0.f, 0.f, 0.f, 0.f);
    const float* vbase = g_v + ((size_t)b * LTc) * DD + h * HDD + cq * 4;

    #pragma unroll
    for (int l = 0; l < 2; l++) {
        const int Wl = l ? W1c : W0c;
        const int Hl = l ? H1c : H0c;
        const int st = l ? N0c : 0;
        const float fW = (float)Wl, fH = (float)Hl;
        #pragma unroll
        for (int pt = 0; pt < 4; pt++) {
            float ox = s_off[h * 16 + l * 8 + pt * 2 + 0];
            float oy = s_off[h * 16 + l * 8 + pt * 2 + 1];
            float aww = wv[l * 4 + pt] * inv;
            float x = (refx + ox / fW) * fW - 0.5f;
            float y = (refy + oy / fH) * fH - 0.5f;
            float x0 = floorf(x), y0 = floorf(y);
            float wx = x - x0, wy = y - y0;
            float cxf = x0 + cxoff, cyf = y0 + cyoff;
            float wcx = cxoff > 0.f ? wx : 1.f - wx;
            float wcy = cyoff > 0.f ? wy : 1.f - wy;
            float wgt = wcx * wcy * aww;
            bool valid = active && (cxf >= 0.f) && (cxf <= fW - 1.f) &&
                         (cyf >= 0.f) && (cyf <= fH - 1.f);
            if (!valid) wgt = 0.f;
            int xi = min(max((int)cxf, 0), Wl - 1);
            int yi = min(max((int)cyf, 0), Hl - 1);
            float4 v4 = *reinterpret_cast<const float4*>(
                vbase + (size_t)(st + yi * Wl + xi) * DD);
            acc.x = fmaf(wgt, v4.x, acc.x);
            acc.y = fmaf(wgt, v4.y, acc.y);
            acc.z = fmaf(wgt, v4.z, acc.z);
            acc.w = fmaf(wgt, v4.w, acc.w);
        }
    }

    // reduce corner partials: lanes {q, q+6, q+12, q+18} -> lane q
    #pragma unroll
    for (int off = 12; off >= 6; off -= 6) {
        acc.x += __shfl_down_sync(0xffffffffu, acc.x, off);
        acc.y += __shfl_down_sync(0xffffffffu, acc.y, off);
        acc.z += __shfl_down_sync(0xffffffffu, acc.z, off);
        acc.w += __shfl_down_sync(0xffffffffu, acc.w, off);
    }
    if (lane < 6) {
        float4 o = make_float4(rnd(acc.x), rnd(acc.y), rnd(acc.z), rnd(acc.w));
        *reinterpret_cast<float4*>(&g_attn[row * DD + h * HDD + lane * 4]) = o;
    }
}

// ---------------- output transpose: both levels in ONE launch ---------------
__global__ void k_out(float* __restrict__ dst) {
    __shared__ float tile[32][33];
    int b = blockIdx.z;
    int bx = blockIdx.x;
    int tokbase, ntok;
    float* base;
    if (bx < N0c / 32) { tokbase = 0;   ntok = N0c; base = dst; }
    else               { tokbase = N0c; ntok = N1c; base = dst + (size_t)NB * DD * N0c; bx -= N0c / 32; }
    int tok0 = bx * 32, d0 = blockIdx.y * 32;
    int tx = threadIdx.x, ty = threadIdx.y;
    tile[ty][tx] = g_src[(size_t)(b * LTc + tokbase + tok0 + ty) * DD + d0 + tx];
    __syncthreads();
    base[(size_t)b * DD * ntok + (size_t)(d0 + ty) * ntok + tok0 + tx] = tile[tx][ty];
}

// ---------------- host orchestration ----------------
extern "C" void kernel_launch(void* const* d_in, const int* in_sizes, int n_in,
                              void* d_out, int out_size) {
    const float* feat0      = (const float*)d_in[0];
    const float* feat1      = (const float*)d_in[1];
    const float* proj_w0    = (const float*)d_in[3];
    const float* proj_b0    = (const float*)d_in[4];
    const float* gn_g0      = (const float*)d_in[5];
    const float* gn_b0      = (const float*)d_in[6];
    const float* proj_w1    = (const float*)d_in[7];
    const float* proj_b1    = (const float*)d_in[8];
    const float* gn_g1      = (const float*)d_in[9];
    const float* gn_b1      = (const float*)d_in[10];
    const float* level_emb  = (const float*)d_in[11];
    const float* so_W       = (const float*)d_in[12];
    const float* so_b       = (const float*)d_in[13];
    const float* aw_W       = (const float*)d_in[14];
    const float* aw_b       = (const float*)d_in[15];
    const float* vp_W       = (const float*)d_in[16];
    const float* vp_b       = (const float*)d_in[17];
    const float* op_W       = (const float*)d_in[18];
    const float* op_b       = (const float*)d_in[19];
    const float* ln1_g      = (const float*)d_in[20];
    const float* ln1_b      = (const float*)d_in[21];
    const float* l1_W       = (const float*)d_in[22];
    const float* l1_b       = (const float*)d_in[23];
    const float* l2_W       = (const float*)d_in[24];
    const float* l2_b       = (const float*)d_in[25];
    const float* ln2_g      = (const float*)d_in[26];
    const float* ln2_b      = (const float*)d_in[27];

    float *p_qrnd, *p_srnd, *p_offaw, *p_v, *p_attn, *p_ffn;
    float *p_wcomb, *p_bcomb, *p_wv, *p_wo, *p_w1, *p_w2;
    cudaGetSymbolAddress((void**)&p_qrnd,  g_qrnd);
    cudaGetSymbolAddress((void**)&p_srnd,  g_srnd);
    cudaGetSymbolAddress((void**)&p_offaw, g_offaw);
    cudaGetSymbolAddress((void**)&p_v,     g_v);
    cudaGetSymbolAddress((void**)&p_attn,  g_attn);
    cudaGetSymbolAddress((void**)&p_ffn,   g_ffn);
    cudaGetSymbolAddress((void**)&p_wcomb, g_wcomb);
    cudaGetSymbolAddress((void**)&p_bcomb, g_bcomb);
    cudaGetSymbolAddress((void**)&p_wv,    g_wv);
    cudaGetSymbolAddress((void**)&p_wo,    g_wo);
    cudaGetSymbolAddress((void**)&p_w1,    g_w1);
    cudaGetSymbolAddress((void**)&p_w2,    g_w2);

    cudaFuncSetAttribute(k_gemm_ln<false>, cudaFuncAttributeMaxDynamicSharedMemorySize, LN_SMEM);
    cudaFuncSetAttribute(k_gemm_ln<true>,  cudaFuncAttributeMaxDynamicSharedMemorySize, LN_SMEM);

    // prelude (4 launches)
    k_init<<<(LTc * DD + 255) / 256, 256>>>(so_W, so_b, aw_W, aw_b, vp_W, op_W, l1_W, l2_W, level_emb);
    k_projall<<<dim3(DD / 64, 180), 256>>>(feat0, feat1, proj_w0, proj_b0, proj_w1, proj_b1);
    k_gn_stats<<<512, 256>>>();
    k_gn_apply<<<(MT * DD + 255) / 256, 256>>>(gn_g0, gn_b0, gn_g1, gn_b1);

    // encoder layers (5 launches each)
    for (int i = 0; i < NLAY; i++) {
        k_gemm_dual<<<dim3(3, MT / 64, 2), 128>>>(
            p_qrnd, p_wcomb + (size_t)i * DD * DD, p_bcomb + (size_t)i * DD, p_offaw,
            p_srnd, p_wv + (size_t)i * DD * DD, vp_b + (size_t)i * DD, p_v);
        k_deform<<<MT, 256>>>();
        k_gemm_ln<false><<<MT / 64, 256, LN_SMEM>>>(
            p_attn, p_wo + (size_t)i * DD * DD, op_b + (size_t)i * DD,
            ln1_g + (size_t)i * DD, ln1_b + (size_t)i * DD, DD);
        k_gemm_main<true, true><<<dim3(4, MT / 64), 128>>>(
            p_srnd, p_w1 + (size_t)i * DD * FFc, l1_b + (size_t)i * FFc, p_ffn, FFc, DD);
        k_gemm_ln<true><<<MT / 64, 256, LN_SMEM>>>(
            p_ffn, p_w2 + (size_t)i * FFc * DD, l2_b + (size_t)i * DD,
            ln2_g + (size_t)i * DD, ln2_b + (size_t)i * DD, FFc);
    }

    // outputs: m0 then m1, each (B, D, H, W) — single launch
    k_out<<<dim3(N0c / 32 + N1c / 32, DD / 32, NB), dim3(32, 32)>>>((float*)d_out);
}